// round 14
// baseline (speedup 1.0000x reference)
#include <cuda_runtime.h>
#include <cuda.h>
#include <cuda_fp16.h>
#include <math.h>
#include <cstdint>

// Problem constants
constexpr int B = 64, T = 256, C = 512, H = 8, D = 64;
constexpr int M = B * T;        // 16384 rows
constexpr int N3 = 3 * H * D;   // 1536 qkv columns

// Scratch (allocation-free: __device__ globals) — fp16 pipeline
__device__ __half g_q[(size_t)B * H * T * D];     // [B,H,T,D]
__device__ __half g_k[(size_t)B * H * T * D];     // [B,H,T,D]
__device__ __half g_v[(size_t)B * H * D * T];     // [B,H,D,T] TRANSPOSED
__device__ __half g_attn[(size_t)M * C];          // [B*T, H*D]
__device__ __half g_wt[(size_t)N3 * C];           // K-major qkv weights
__device__ __half g_wot[(size_t)C * C];           // K-major wo
__device__ float  g_bcat[N3];                     // concatenated qkv bias (fp32)
__device__ __half g_xr[(size_t)M * C];            // fp16-rounded x

// ---------------------------------------------------------------------------
// Helpers
// ---------------------------------------------------------------------------
__device__ __forceinline__ float ex2f(float x) {
    float y;
    asm("ex2.approx.f32 %0, %1;" : "=f"(y) : "f"(x));
    return y;
}
__device__ __forceinline__ uint32_t smem_u32(const void* p) {
    uint32_t a;
    asm("{ .reg .u64 t; cvta.to.shared.u64 t, %1; cvt.u32.u64 %0, t; }" : "=r"(a) : "l"(p));
    return a;
}
// m16n8k16 fp16 MMA, fp32 accumulate.
__device__ __forceinline__ void mma_f16(float* c, const uint32_t* a, const uint32_t* b) {
    asm volatile(
        "mma.sync.aligned.m16n8k16.row.col.f32.f16.f16.f32 "
        "{%0,%1,%2,%3}, {%4,%5,%6,%7}, {%8,%9}, {%0,%1,%2,%3};"
        : "+f"(c[0]), "+f"(c[1]), "+f"(c[2]), "+f"(c[3])
        : "r"(a[0]), "r"(a[1]), "r"(a[2]), "r"(a[3]), "r"(b[0]), "r"(b[1]));
}
#define LDM4(r0, r1, r2, r3, addr)                                              \
    asm volatile("ldmatrix.sync.aligned.m8n8.x4.shared.b16 {%0,%1,%2,%3}, [%4];" \
                 : "=r"(r0), "=r"(r1), "=r"(r2), "=r"(r3) : "r"(addr))

__device__ __forceinline__ void cp16(uint32_t dst, const void* src) {
    asm volatile("cp.async.cg.shared.global [%0], [%1], 16;" :: "r"(dst), "l"(src));
}
#define CP_COMMIT() asm volatile("cp.async.commit_group;" ::: "memory")
#define CP_WAIT1()  asm volatile("cp.async.wait_group 1;" ::: "memory")

// ---------------------------------------------------------------------------
// Fused prep kernel (unchanged)
// ---------------------------------------------------------------------------
constexpr int NCVT = (M * C / 4) / 256;      // 8192
constexpr int NTQ  = 16 * 2 * 24;            // 768
constexpr int NTW  = 16 * 16;                // 256
constexpr int PREP_BLOCKS = NCVT + NTQ + NTW + 6;

__global__ void __launch_bounds__(256) prep_kernel(
    const float4* __restrict__ x,
    const float* __restrict__ wq, const float* __restrict__ wk,
    const float* __restrict__ wv, const float* __restrict__ wo,
    const float* __restrict__ bq, const float* __restrict__ bk,
    const float* __restrict__ bv)
{
    __shared__ float t[32][33];
    const int blk = blockIdx.x;
    const int tid = threadIdx.x;

    if (blk < NCVT) {
        int i = blk * 256 + tid;
        float4 v = x[i];
        __half2* dst = (__half2*)g_xr + (size_t)i * 2;
        dst[0] = __floats2half2_rn(v.x, v.y);
        dst[1] = __floats2half2_rn(v.z, v.w);
        return;
    }
    const int tx = tid & 31, ty = tid >> 5;
    if (blk < NCVT + NTQ) {
        const int r = blk - NCVT;
        const int bx = r & 15, by = (r >> 4) & 1, bz = r >> 5;
        const int kind = bz >> 3, h = bz & 7;
        const float* src = ((kind == 0) ? wq : (kind == 1) ? wk : wv) + (size_t)h * C * D;
        const int c0 = bx * 32, d0 = by * 32;
        #pragma unroll
        for (int i = 0; i < 32; i += 8)
            t[ty + i][tx] = src[(size_t)(c0 + ty + i) * D + d0 + tx];
        __syncthreads();
        __half* dst = g_wt + (size_t)(kind * 512 + h * 64) * C;
        #pragma unroll
        for (int i = 0; i < 32; i += 8)
            dst[(size_t)(d0 + ty + i) * C + c0 + tx] = __float2half_rn(t[tx][ty + i]);
        return;
    }
    if (blk < NCVT + NTQ + NTW) {
        const int r = blk - NCVT - NTQ;
        const int n0 = (r & 15) * 32, k0 = (r >> 4) * 32;
        #pragma unroll
        for (int i = 0; i < 32; i += 8)
            t[ty + i][tx] = wo[(size_t)(k0 + ty + i) * C + n0 + tx];
        __syncthreads();
        #pragma unroll
        for (int i = 0; i < 32; i += 8)
            g_wot[(size_t)(n0 + ty + i) * C + k0 + tx] = __float2half_rn(t[tx][ty + i]);
        return;
    }
    {
        const int idx = (blk - NCVT - NTQ - NTW) * 256 + tid;
        if (idx < N3) {
            int kind = idx >> 9, i = idx & 511;
            g_bcat[idx] = (kind == 0) ? bq[i] : (kind == 1) ? bk[i] : bv[i];
        }
    }
}

// ---------------------------------------------------------------------------
// fp16 mma.sync GEMM (m16n8k16), BK=64 halfs, cp.async 3-stage + ldmatrix.
// CTA 128x128, 8 warps (wm 2 x wn 4), warp tile 64x32.
// 8 K-stages; 4 k16-steps (32 HMMA/warp) between barriers.
// ---------------------------------------------------------------------------
constexpr int ROWB = 144;                         // bytes/row: 128 data + 16 pad
constexpr int TILE_BYTES = 128 * ROWB;            // 18432
constexpr int STAGE_BYTES = 2 * TILE_BYTES;       // 36864
constexpr int GSTAGES = 3;
constexpr int SMEM_GEMM_BYTES = GSTAGES * STAGE_BYTES;   // 110,592 B -> 2 CTA/SM

__global__ void __launch_bounds__(256, 2) gemm_mma_kernel(
    const float* __restrict__ bo_in, float* __restrict__ outp, int mode)
{
    extern __shared__ char smc[];
    const uint32_t smb = smem_u32(smc);
    const int tid = threadIdx.x;
    const int wid = tid >> 5;
    const int lid = tid & 31;
    const int gid = lid >> 2, tig = lid & 3;
    const int lg = lid >> 3, lr8 = lid & 7;
    const int wm = wid & 1;
    const int wn = wid >> 1;

    const __half* A    = (mode == 0) ? g_xr : g_attn;
    const __half* Bt   = (mode == 0) ? g_wt : g_wot;
    const float*  bias = (mode == 0) ? g_bcat : bo_in;

    const int n0 = blockIdx.x * 128;
    const int m0 = blockIdx.y * 128;

    float acc[4][4][4];
    #pragma unroll
    for (int i = 0; i < 4; i++)
        #pragma unroll
        for (int j = 0; j < 4; j++)
            #pragma unroll
            for (int q = 0; q < 4; q++) acc[i][j][q] = 0.f;

    // cp.async: 128 rows x 8 16B-chunks = 1024 chunks per tile; 4/thread
    auto issue = [&](int s) {
        const int k0 = s * 64;                       // halfs
        const uint32_t ab = smb + (uint32_t)((s % GSTAGES) * STAGE_BYTES);
        const uint32_t bb = ab + TILE_BYTES;
        #pragma unroll
        for (int p = 0; p < 4; p++) {
            const int c = tid + p * 256;
            const int row = c >> 3, col = c & 7;
            const uint32_t off = (uint32_t)(row * ROWB + col * 16);
            cp16(ab + off, A  + (size_t)(m0 + row) * C + col * 8 + k0);
            cp16(bb + off, Bt + (size_t)(n0 + row) * C + col * 8 + k0);
        }
    };

    uint32_t aoff[4], boff[2];
    #pragma unroll
    for (int mf = 0; mf < 4; mf++) {
        const int row = wm * 64 + mf * 16 + (lg & 1) * 8 + lr8;
        aoff[mf] = (uint32_t)(row * ROWB + (lg >> 1) * 16);
    }
    #pragma unroll
    for (int p = 0; p < 2; p++) {
        const int row = wn * 32 + p * 16 + (lg >> 1) * 8 + lr8;
        boff[p] = (uint32_t)(row * ROWB + (lg & 1) * 16);
    }

    issue(0); CP_COMMIT();
    issue(1); CP_COMMIT();

    for (int s = 0; s < 8; s++) {
        CP_WAIT1();
        __syncthreads();
        if (s + 2 < 8) issue(s + 2);
        CP_COMMIT();

        const uint32_t ab = smb + (uint32_t)((s % GSTAGES) * STAGE_BYTES);
        const uint32_t bb = ab + TILE_BYTES;
        #pragma unroll
        for (int ks = 0; ks < 4; ks++) {             // 4 x k16 per 64-half stage
            const uint32_t kb = (uint32_t)ks * 32;   // 16 halfs = 32 bytes
            uint32_t af[4][4], bf[2][4];
            #pragma unroll
            for (int mf = 0; mf < 4; mf++)
                LDM4(af[mf][0], af[mf][1], af[mf][2], af[mf][3], ab + aoff[mf] + kb);
            #pragma unroll
            for (int p = 0; p < 2; p++)
                LDM4(bf[p][0], bf[p][1], bf[p][2], bf[p][3], bb + boff[p] + kb);
            #pragma unroll
            for (int mf = 0; mf < 4; mf++)
                #pragma unroll
                for (int p = 0; p < 2; p++) {
                    mma_f16(acc[mf][2 * p],     af[mf], &bf[p][0]);
                    mma_f16(acc[mf][2 * p + 1], af[mf], &bf[p][2]);
                }
        }
    }

    #pragma unroll
    for (int nf = 0; nf < 4; nf++) {
        const int j = n0 + wn * 32 + nf * 8 + 2 * tig;
        const float b0 = bias[j], b1 = bias[j + 1];
        #pragma unroll
        for (int mf = 0; mf < 4; mf++) {
            const int mrow0 = m0 + wm * 64 + mf * 16 + gid;
            #pragma unroll
            for (int half = 0; half < 2; half++) {
                const int m = mrow0 + half * 8;
                const float vx = acc[mf][nf][half * 2 + 0] + b0;
                const float vy = acc[mf][nf][half * 2 + 1] + b1;
                if (mode == 0) {
                    const int kind = j >> 9;
                    const int hh = (j >> 6) & 7;
                    const int dd = j & 63;
                    const int bb2 = m >> 8;
                    const int tt = m & 255;
                    if (kind == 2) {   // V transposed: [b,h,d,t]
                        __half* dst = g_v + (((size_t)(bb2 * H + hh)) * D + dd) * T + tt;
                        dst[0] = __float2half_rn(vx);
                        dst[T] = __float2half_rn(vy);
                    } else {
                        __half* bufp = (kind == 0) ? g_q : g_k;
                        __half* dst = bufp + (((size_t)(bb2 * H + hh)) * T + tt) * D + dd;
                        *(__half2*)dst = __floats2half2_rn(vx, vy);
                    }
                } else {
                    float* dst = outp + (size_t)m * C + j;
                    *(float2*)dst = make_float2(vx, vy);
                }
            }
        }
    }
}

// ---------------------------------------------------------------------------
// fp16 online-softmax attention (unchanged from R13)
// ---------------------------------------------------------------------------
constexpr int QROWB = 144;   // Q/K row bytes (128 data + 16 pad)
constexpr int CROWB = 272;   // St/Vt row bytes (256 data + 16 pad)
constexpr int AQ_B  = 0;                     // Qs 64*144  = 9216
constexpr int AKV_B = 9216;                  // K 128*144=18432 | Vt 64*272=17408
constexpr int AS_B  = AKV_B + 18432;         // St 64*272 = 17408
constexpr int APM_B = AS_B + 17408;          // pmax f32[4][64] = 1024
constexpr int APS_B = APM_B + 1024;          // psum f32[4][64] = 1024
constexpr int SMEM_ATTN = APS_B + 1024;      // 47,104 B -> 2 CTA/SM

__global__ void __launch_bounds__(256, 2) attn_kernel()
{
    extern __shared__ char smc[];
    const uint32_t smb = smem_u32(smc);
    float* pmx = (float*)(smc + APM_B);
    float* psm = (float*)(smc + APS_B);

    const int qt  = blockIdx.x;            // 0..3
    const int hh  = blockIdx.y;
    const int bb  = blockIdx.z;
    const int tid = threadIdx.x;
    const int wid = tid >> 5;
    const int lid = tid & 31;
    const int gid = lid >> 2, tig = lid & 3;
    const int lg = lid >> 3, lr8 = lid & 7;
    const int wm = wid & 1;                // 32 q-rows each
    const int wn = wid >> 1;               // 4 col/d groups
    const int t0 = qt * 64;
    const int S_lim = t0 + 64;
    const int nchunks = (S_lim + 127) >> 7;

    const __half* qp = g_q + ((size_t)(bb * H + hh)) * T * D;
    const __half* kp = g_k + ((size_t)(bb * H + hh)) * T * D;
    const __half* vp = g_v + ((size_t)(bb * H + hh)) * D * T;   // [d][t]

    for (int idx = tid; idx < 64 * 8; idx += 256) {
        const int i = idx >> 3, c = idx & 7;
        *(uint4*)(smc + AQ_B + i * QROWB + c * 16) =
            *(const uint4*)(qp + (size_t)(t0 + i) * D + c * 8);
    }

    float O[2][2][4];
    float m_run[2][2], l_run[2][2];
    #pragma unroll
    for (int i = 0; i < 2; i++)
        #pragma unroll
        for (int j = 0; j < 2; j++) {
            m_run[i][j] = -1e30f; l_run[i][j] = 0.f;
            #pragma unroll
            for (int q = 0; q < 4; q++) O[i][j][q] = 0.f;
        }

    uint32_t qoff[2];
    #pragma unroll
    for (int mf = 0; mf < 2; mf++) {
        const int row = wm * 32 + mf * 16 + (lg & 1) * 8 + lr8;
        qoff[mf] = smb + (uint32_t)(AQ_B + row * QROWB + (lg >> 1) * 16);
    }
    const float C1L = 0.18033688011112042f;    // 0.125 * log2(e)
    const int kmax_g = t0 + wm * 32 + 32;      // keys beyond have P=0 for this warp

    for (int c = 0; c < nchunks; c++) {
        const int s0 = c << 7;
        const int sc = min(128, S_lim - s0);       // 64 or 128
        const int NWc = sc >> 2;                   // 16 or 32
        const int nfmax = NWc >> 3;                // 2 or 4
        const int npair = nfmax >> 1;              // 1 or 2
        const int t_hi = t0 + wm * 32 + 31;

        for (int idx = tid; idx < sc * 8; idx += 256) {
            const int s = idx >> 3, cc = idx & 7;
            *(uint4*)(smc + AKV_B + s * QROWB + cc * 16) =
                *(const uint4*)(kp + (size_t)(s0 + s) * D + cc * 8);
        }
        __syncthreads();

        float acc[2][4][4];
        #pragma unroll
        for (int i = 0; i < 2; i++)
            #pragma unroll
            for (int j = 0; j < 4; j++)
                #pragma unroll
                for (int q = 0; q < 4; q++) acc[i][j][q] = 0.f;

        #pragma unroll
        for (int ks = 0; ks < 4; ks++) {
            const uint32_t kb = (uint32_t)ks * 32;
            uint32_t af[2][4];
            #pragma unroll
            for (int mf = 0; mf < 2; mf++)
                LDM4(af[mf][0], af[mf][1], af[mf][2], af[mf][3], qoff[mf] + kb);
            #pragma unroll
            for (int p = 0; p < 2; p++) {
                if (p >= npair) break;
                const int n_lo = wn * NWc + p * 16;
                const int n_abs = s0 + n_lo;
                if (n_abs > t_hi) continue;
                const int rowk = n_lo + (lg >> 1) * 8 + lr8;
                uint32_t bf[4];
                LDM4(bf[0], bf[1], bf[2], bf[3],
                     smb + (uint32_t)(AKV_B + rowk * QROWB + (lg & 1) * 16) + kb);
                #pragma unroll
                for (int mf = 0; mf < 2; mf++) {
                    mma_f16(acc[mf][2 * p],     af[mf], &bf[0]);
                    if (n_abs + 8 <= t_hi)
                        mma_f16(acc[mf][2 * p + 1], af[mf], &bf[2]);
                }
            }
        }

        #pragma unroll
        for (int mf = 0; mf < 2; mf++) {
            const int r0 = wm * 32 + mf * 16 + gid;
            const int tg0 = t0 + r0, tg1 = tg0 + 8;
            float w0 = -1e30f, w1 = -1e30f;
            #pragma unroll
            for (int nf = 0; nf < 4; nf++) {
                if (nf >= nfmax) break;
                const int sA = s0 + wn * NWc + nf * 8 + 2 * tig;
                float* a = acc[mf][nf];
                a[0] = (sA     <= tg0) ? a[0] : -1e30f;
                a[1] = (sA + 1 <= tg0) ? a[1] : -1e30f;
                a[2] = (sA     <= tg1) ? a[2] : -1e30f;
                a[3] = (sA + 1 <= tg1) ? a[3] : -1e30f;
                w0 = fmaxf(w0, fmaxf(a[0], a[1]));
                w1 = fmaxf(w1, fmaxf(a[2], a[3]));
            }
            w0 = fmaxf(w0, __shfl_xor_sync(0xffffffffu, w0, 1));
            w0 = fmaxf(w0, __shfl_xor_sync(0xffffffffu, w0, 2));
            w1 = fmaxf(w1, __shfl_xor_sync(0xffffffffu, w1, 1));
            w1 = fmaxf(w1, __shfl_xor_sync(0xffffffffu, w1, 2));
            if (tig == 0) {
                pmx[wn * 64 + r0]     = w0;
                pmx[wn * 64 + r0 + 8] = w1;
            }
        }
        __syncthreads();

        #pragma unroll
        for (int mf = 0; mf < 2; mf++) {
            const int r0 = wm * 32 + mf * 16 + gid;
            #pragma unroll
            for (int half = 0; half < 2; half++) {
                const int lrow = r0 + half * 8;
                float mc = fmaxf(fmaxf(pmx[lrow], pmx[64 + lrow]),
                                 fmaxf(pmx[128 + lrow], pmx[192 + lrow]));
                float mnew = fmaxf(m_run[mf][half], mc);
                float alpha = ex2f((m_run[mf][half] - mnew) * C1L);
                m_run[mf][half] = mnew;
                l_run[mf][half] *= alpha;
                #pragma unroll
                for (int nf = 0; nf < 2; nf++) {
                    O[mf][nf][half * 2 + 0] *= alpha;
                    O[mf][nf][half * 2 + 1] *= alpha;
                }
                float ps = 0.f;
                #pragma unroll
                for (int nf = 0; nf < 4; nf++) {
                    if (nf >= nfmax) break;
                    const int sl = wn * NWc + nf * 8 + 2 * tig;
                    float* a = acc[mf][nf];
                    float e0 = ex2f((a[half * 2 + 0] - mnew) * C1L);
                    float e1 = ex2f((a[half * 2 + 1] - mnew) * C1L);
                    ps += e0 + e1;
                    *(__half2*)(smc + AS_B + lrow * CROWB + sl * 2) =
                        __floats2half2_rn(e0, e1);
                }
                ps += __shfl_xor_sync(0xffffffffu, ps, 1);
                ps += __shfl_xor_sync(0xffffffffu, ps, 2);
                if (tig == 0) psm[wn * 64 + lrow] = ps;
            }
        }
        __syncthreads();   // St/psm ready; K dead

        {
            const int csh = (sc == 128) ? 4 : 3;       // 16B chunks per Vt row
            for (int idx = tid; idx < (64 << csh); idx += 256) {
                const int d = idx >> csh, cc = idx & ((1 << csh) - 1);
                *(uint4*)(smc + AKV_B + d * CROWB + cc * 16) =
                    *(const uint4*)(vp + (size_t)d * T + s0 + cc * 8);
            }
        }
        #pragma unroll
        for (int mf = 0; mf < 2; mf++) {
            const int r0 = wm * 32 + mf * 16 + gid;
            #pragma unroll
            for (int half = 0; half < 2; half++) {
                const int lrow = r0 + half * 8;
                l_run[mf][half] += psm[lrow] + psm[64 + lrow] +
                                   psm[128 + lrow] + psm[192 + lrow];
            }
        }
        __syncthreads();   // V ready

        {
            uint32_t soff[2];
            #pragma unroll
            for (int mf = 0; mf < 2; mf++) {
                const int row = wm * 32 + mf * 16 + (lg & 1) * 8 + lr8;
                soff[mf] = smb + (uint32_t)(AS_B + row * CROWB + (lg >> 1) * 16);
            }
            const int rowv = wn * 16 + (lg >> 1) * 8 + lr8;
            const uint32_t voff = smb + (uint32_t)(AKV_B + rowv * CROWB + (lg & 1) * 16);

            const int kloc = min(sc, kmax_g - s0);     // nonzero P cols
            const int kst = kloc >> 4;
            for (int ks = 0; ks < kst; ks++) {
                const uint32_t kb = (uint32_t)ks * 32;
                uint32_t af[2][4], bf[4];
                LDM4(bf[0], bf[1], bf[2], bf[3], voff + kb);
                #pragma unroll
                for (int mf = 0; mf < 2; mf++) {
                    LDM4(af[mf][0], af[mf][1], af[mf][2], af[mf][3], soff[mf] + kb);
                    mma_f16(O[mf][0], af[mf], &bf[0]);
                    mma_f16(O[mf][1], af[mf], &bf[2]);
                }
            }
        }
        __syncthreads();   // KV/St free for next chunk
    }

    #pragma unroll
    for (int mf = 0; mf < 2; mf++) {
        const int row0 = wm * 32 + mf * 16 + gid;
        #pragma unroll
        for (int half = 0; half < 2; half++) {
            const int i = row0 + half * 8;
            const float inv = 1.f / l_run[mf][half];
            #pragma unroll
            for (int nf = 0; nf < 2; nf++) {
                const int col = wn * 16 + nf * 8 + 2 * tig;
                *(__half2*)(g_attn + ((size_t)bb * T + t0 + i) * C + hh * D + col) =
                    __floats2half2_rn(O[mf][nf][half * 2 + 0] * inv,
                                      O[mf][nf][half * 2 + 1] * inv);
            }
        }
    }
}

// ---------------------------------------------------------------------------
extern "C" void kernel_launch(void* const* d_in, const int* in_sizes, int n_in,
                              void* d_out, int out_size)
{
    const float* x  = (const float*)d_in[0];
    const float* wq = (const float*)d_in[1];
    const float* wk = (const float*)d_in[2];
    const float* wv = (const float*)d_in[3];
    const float* bq = (const float*)d_in[4];
    const float* bk = (const float*)d_in[5];
    const float* bv = (const float*)d_in[6];
    const float* wo = (const float*)d_in[7];
    const float* bo = (const float*)d_in[8];
    float* out = (float*)d_out;

    cudaFuncSetAttribute(attn_kernel, cudaFuncAttributeMaxDynamicSharedMemorySize,
                         SMEM_ATTN);
    cudaFuncSetAttribute(gemm_mma_kernel, cudaFuncAttributeMaxDynamicSharedMemorySize,
                         SMEM_GEMM_BYTES);

    prep_kernel<<<PREP_BLOCKS, 256>>>((const float4*)x, wq, wk, wv, wo, bq, bk, bv);
    gemm_mma_kernel<<<dim3(N3 / 128, M / 128), 256, SMEM_GEMM_BYTES>>>(nullptr, nullptr, 0);
    attn_kernel<<<dim3(T / 64, H, B), 256, SMEM_ATTN>>>();
    gemm_mma_kernel<<<dim3(C / 128, M / 128), 256, SMEM_GEMM_BYTES>>>(bo, out, 1);
}

// round 15
// speedup vs baseline: 1.5760x; 1.5760x over previous
#include <cuda_runtime.h>
#include <cuda.h>
#include <cuda_fp16.h>
#include <math.h>
#include <cstdint>

// Problem constants
constexpr int B = 64, T = 256, C = 512, H = 8, D = 64;
constexpr int M = B * T;        // 16384 rows
constexpr int N3 = 3 * H * D;   // 1536 qkv columns

// Scratch (allocation-free: __device__ globals) — fp16 pipeline
__device__ __half g_q[(size_t)B * H * T * D];     // [B,H,T,D]
__device__ __half g_k[(size_t)B * H * T * D];     // [B,H,T,D]
__device__ __half g_v[(size_t)B * H * T * D];     // [B,H,T,D]  (row-major now)
__device__ __half g_attn[(size_t)M * C];          // [B*T, H*D]
__device__ __half g_wt[(size_t)N3 * C];           // K-major qkv weights
__device__ __half g_wot[(size_t)C * C];           // K-major wo
__device__ float  g_bcat[N3];                     // concatenated qkv bias (fp32)
__device__ __half g_xr[(size_t)M * C];            // fp16-rounded x

// ---------------------------------------------------------------------------
// Helpers
// ---------------------------------------------------------------------------
__device__ __forceinline__ float ex2f(float x) {
    float y;
    asm("ex2.approx.f32 %0, %1;" : "=f"(y) : "f"(x));
    return y;
}
__device__ __forceinline__ uint32_t smem_u32(const void* p) {
    uint32_t a;
    asm("{ .reg .u64 t; cvta.to.shared.u64 t, %1; cvt.u32.u64 %0, t; }" : "=r"(a) : "l"(p));
    return a;
}
// m16n8k16 fp16 MMA, fp32 accumulate.
__device__ __forceinline__ void mma_f16(float* c, const uint32_t* a, const uint32_t* b) {
    asm volatile(
        "mma.sync.aligned.m16n8k16.row.col.f32.f16.f16.f32 "
        "{%0,%1,%2,%3}, {%4,%5,%6,%7}, {%8,%9}, {%0,%1,%2,%3};"
        : "+f"(c[0]), "+f"(c[1]), "+f"(c[2]), "+f"(c[3])
        : "r"(a[0]), "r"(a[1]), "r"(a[2]), "r"(a[3]), "r"(b[0]), "r"(b[1]));
}
#define LDM4(r0, r1, r2, r3, addr)                                              \
    asm volatile("ldmatrix.sync.aligned.m8n8.x4.shared.b16 {%0,%1,%2,%3}, [%4];" \
                 : "=r"(r0), "=r"(r1), "=r"(r2), "=r"(r3) : "r"(addr))
#define LDM4T(r0, r1, r2, r3, addr)                                                   \
    asm volatile("ldmatrix.sync.aligned.m8n8.x4.trans.shared.b16 {%0,%1,%2,%3}, [%4];" \
                 : "=r"(r0), "=r"(r1), "=r"(r2), "=r"(r3) : "r"(addr))

__device__ __forceinline__ void cp16(uint32_t dst, const void* src) {
    asm volatile("cp.async.cg.shared.global [%0], [%1], 16;" :: "r"(dst), "l"(src));
}
#define CP_COMMIT() asm volatile("cp.async.commit_group;" ::: "memory")
#define CP_WAIT1()  asm volatile("cp.async.wait_group 1;" ::: "memory")

// ---------------------------------------------------------------------------
// Fused prep kernel (unchanged from R13)
// ---------------------------------------------------------------------------
constexpr int NCVT = (M * C / 4) / 256;      // 8192
constexpr int NTQ  = 16 * 2 * 24;            // 768
constexpr int NTW  = 16 * 16;                // 256
constexpr int PREP_BLOCKS = NCVT + NTQ + NTW + 6;

__global__ void __launch_bounds__(256) prep_kernel(
    const float4* __restrict__ x,
    const float* __restrict__ wq, const float* __restrict__ wk,
    const float* __restrict__ wv, const float* __restrict__ wo,
    const float* __restrict__ bq, const float* __restrict__ bk,
    const float* __restrict__ bv)
{
    __shared__ float t[32][33];
    const int blk = blockIdx.x;
    const int tid = threadIdx.x;

    if (blk < NCVT) {
        int i = blk * 256 + tid;
        float4 v = x[i];
        __half2* dst = (__half2*)g_xr + (size_t)i * 2;
        dst[0] = __floats2half2_rn(v.x, v.y);
        dst[1] = __floats2half2_rn(v.z, v.w);
        return;
    }
    const int tx = tid & 31, ty = tid >> 5;
    if (blk < NCVT + NTQ) {
        const int r = blk - NCVT;
        const int bx = r & 15, by = (r >> 4) & 1, bz = r >> 5;
        const int kind = bz >> 3, h = bz & 7;
        const float* src = ((kind == 0) ? wq : (kind == 1) ? wk : wv) + (size_t)h * C * D;
        const int c0 = bx * 32, d0 = by * 32;
        #pragma unroll
        for (int i = 0; i < 32; i += 8)
            t[ty + i][tx] = src[(size_t)(c0 + ty + i) * D + d0 + tx];
        __syncthreads();
        __half* dst = g_wt + (size_t)(kind * 512 + h * 64) * C;
        #pragma unroll
        for (int i = 0; i < 32; i += 8)
            dst[(size_t)(d0 + ty + i) * C + c0 + tx] = __float2half_rn(t[tx][ty + i]);
        return;
    }
    if (blk < NCVT + NTQ + NTW) {
        const int r = blk - NCVT - NTQ;
        const int n0 = (r & 15) * 32, k0 = (r >> 4) * 32;
        #pragma unroll
        for (int i = 0; i < 32; i += 8)
            t[ty + i][tx] = wo[(size_t)(k0 + ty + i) * C + n0 + tx];
        __syncthreads();
        #pragma unroll
        for (int i = 0; i < 32; i += 8)
            g_wot[(size_t)(n0 + ty + i) * C + k0 + tx] = __float2half_rn(t[tx][ty + i]);
        return;
    }
    {
        const int idx = (blk - NCVT - NTQ - NTW) * 256 + tid;
        if (idx < N3) {
            int kind = idx >> 9, i = idx & 511;
            g_bcat[idx] = (kind == 0) ? bq[i] : (kind == 1) ? bk[i] : bv[i];
        }
    }
}

// ---------------------------------------------------------------------------
// fp16 mma.sync GEMM (m16n8k16) — R13 configuration (BK=32 halfs, 16 stages).
// Epilogue mode 0 now uniform half2 stores for q/k/v ([B,H,T,D] all).
// ---------------------------------------------------------------------------
constexpr int ROWB = 80;                          // bytes per smem row (64 data + 16 pad)
constexpr int TILE_BYTES = 128 * ROWB;            // 10240
constexpr int STAGE_BYTES = 2 * TILE_BYTES;       // 20480
constexpr int GSTAGES = 3;
constexpr int SMEM_GEMM_BYTES = GSTAGES * STAGE_BYTES;   // 61,440 B -> 2 CTA/SM

__global__ void __launch_bounds__(256, 2) gemm_mma_kernel(
    const float* __restrict__ bo_in, float* __restrict__ outp, int mode)
{
    extern __shared__ char smc[];
    const uint32_t smb = smem_u32(smc);
    const int tid = threadIdx.x;
    const int wid = tid >> 5;
    const int lid = tid & 31;
    const int gid = lid >> 2, tig = lid & 3;
    const int lg = lid >> 3, lr8 = lid & 7;
    const int wm = wid & 1;
    const int wn = wid >> 1;

    const __half* A    = (mode == 0) ? g_xr : g_attn;
    const __half* Bt   = (mode == 0) ? g_wt : g_wot;
    const float*  bias = (mode == 0) ? g_bcat : bo_in;

    const int n0 = blockIdx.x * 128;
    const int m0 = blockIdx.y * 128;

    float acc[4][4][4];
    #pragma unroll
    for (int i = 0; i < 4; i++)
        #pragma unroll
        for (int j = 0; j < 4; j++)
            #pragma unroll
            for (int q = 0; q < 4; q++) acc[i][j][q] = 0.f;

    auto issue = [&](int s) {
        const int k0 = s * 32;                       // halfs
        const uint32_t ab = smb + (uint32_t)((s % GSTAGES) * STAGE_BYTES);
        const uint32_t bb = ab + TILE_BYTES;
        #pragma unroll
        for (int p = 0; p < 2; p++) {
            const int c = tid + p * 256;
            const int row = c >> 2, col = c & 3;
            const uint32_t off = (uint32_t)(row * ROWB + col * 16);
            cp16(ab + off, A  + (size_t)(m0 + row) * C + col * 8 + k0);
            cp16(bb + off, Bt + (size_t)(n0 + row) * C + col * 8 + k0);
        }
    };

    uint32_t aoff[4], boff[2];
    #pragma unroll
    for (int mf = 0; mf < 4; mf++) {
        const int row = wm * 64 + mf * 16 + (lg & 1) * 8 + lr8;
        aoff[mf] = (uint32_t)(row * ROWB + (lg >> 1) * 16);
    }
    #pragma unroll
    for (int p = 0; p < 2; p++) {
        const int row = wn * 32 + p * 16 + (lg >> 1) * 8 + lr8;
        boff[p] = (uint32_t)(row * ROWB + (lg & 1) * 16);
    }

    issue(0); CP_COMMIT();
    issue(1); CP_COMMIT();

    for (int s = 0; s < 16; s++) {
        CP_WAIT1();
        __syncthreads();
        if (s + 2 < 16) issue(s + 2);
        CP_COMMIT();

        const uint32_t ab = smb + (uint32_t)((s % GSTAGES) * STAGE_BYTES);
        const uint32_t bb = ab + TILE_BYTES;
        #pragma unroll
        for (int ks = 0; ks < 2; ks++) {
            const uint32_t kb = (uint32_t)ks * 32;
            uint32_t af[4][4], bf[2][4];
            #pragma unroll
            for (int mf = 0; mf < 4; mf++)
                LDM4(af[mf][0], af[mf][1], af[mf][2], af[mf][3], ab + aoff[mf] + kb);
            #pragma unroll
            for (int p = 0; p < 2; p++)
                LDM4(bf[p][0], bf[p][1], bf[p][2], bf[p][3], bb + boff[p] + kb);
            #pragma unroll
            for (int mf = 0; mf < 4; mf++)
                #pragma unroll
                for (int p = 0; p < 2; p++) {
                    mma_f16(acc[mf][2 * p],     af[mf], &bf[p][0]);
                    mma_f16(acc[mf][2 * p + 1], af[mf], &bf[p][2]);
                }
        }
    }

    #pragma unroll
    for (int nf = 0; nf < 4; nf++) {
        const int j = n0 + wn * 32 + nf * 8 + 2 * tig;
        const float b0 = bias[j], b1 = bias[j + 1];
        #pragma unroll
        for (int mf = 0; mf < 4; mf++) {
            const int mrow0 = m0 + wm * 64 + mf * 16 + gid;
            #pragma unroll
            for (int half = 0; half < 2; half++) {
                const int m = mrow0 + half * 8;
                const float vx = acc[mf][nf][half * 2 + 0] + b0;
                const float vy = acc[mf][nf][half * 2 + 1] + b1;
                if (mode == 0) {
                    const int kind = j >> 9;
                    const int hh = (j >> 6) & 7;
                    const int dd = j & 63;
                    const int bb2 = m >> 8;
                    const int tt = m & 255;
                    __half* bufp = (kind == 0) ? g_q : (kind == 1) ? g_k : g_v;
                    __half* dst = bufp + (((size_t)(bb2 * H + hh)) * T + tt) * D + dd;
                    *(__half2*)dst = __floats2half2_rn(vx, vy);
                } else {
                    float* dst = outp + (size_t)m * C + j;
                    *(float2*)dst = make_float2(vx, vy);
                }
            }
        }
    }
}

// ---------------------------------------------------------------------------
// fp16 online-softmax attention. V now [b,h,t,d]; PV uses ldmatrix.trans.
// One block per (64 q-rows, h, b), 8 warps (wm 2 x wn 4). 2 CTA/SM.
// ---------------------------------------------------------------------------
constexpr int QROWB = 144;   // Q/K/V row bytes (128 data + 16 pad)
constexpr int CROWB = 272;   // St row bytes (256 data + 16 pad)
constexpr int AQ_B  = 0;                     // Qs 64*144  = 9216
constexpr int AKV_B = 9216;                  // K/V chunk 128*144 = 18432
constexpr int AS_B  = AKV_B + 18432;         // St 64*272 = 17408
constexpr int APM_B = AS_B + 17408;          // pmax f32[4][64] = 1024
constexpr int APS_B = APM_B + 1024;          // psum f32[4][64] = 1024
constexpr int SMEM_ATTN = APS_B + 1024;      // 47,104 B -> 2 CTA/SM

__global__ void __launch_bounds__(256, 2) attn_kernel()
{
    extern __shared__ char smc[];
    const uint32_t smb = smem_u32(smc);
    float* pmx = (float*)(smc + APM_B);
    float* psm = (float*)(smc + APS_B);

    const int qt  = blockIdx.x;            // 0..3
    const int hh  = blockIdx.y;
    const int bb  = blockIdx.z;
    const int tid = threadIdx.x;
    const int wid = tid >> 5;
    const int lid = tid & 31;
    const int gid = lid >> 2, tig = lid & 3;
    const int lg = lid >> 3, lr8 = lid & 7;
    const int wm = wid & 1;                // 32 q-rows each
    const int wn = wid >> 1;               // 4 col/d groups
    const int t0 = qt * 64;
    const int S_lim = t0 + 64;
    const int nchunks = (S_lim + 127) >> 7;

    const __half* qp = g_q + ((size_t)(bb * H + hh)) * T * D;
    const __half* kp = g_k + ((size_t)(bb * H + hh)) * T * D;
    const __half* vp = g_v + ((size_t)(bb * H + hh)) * T * D;   // [t][d]

    // load Q once
    for (int idx = tid; idx < 64 * 8; idx += 256) {
        const int i = idx >> 3, c = idx & 7;
        *(uint4*)(smc + AQ_B + i * QROWB + c * 16) =
            *(const uint4*)(qp + (size_t)(t0 + i) * D + c * 8);
    }

    float O[2][2][4];
    float m_run[2][2], l_run[2][2];
    #pragma unroll
    for (int i = 0; i < 2; i++)
        #pragma unroll
        for (int j = 0; j < 2; j++) {
            m_run[i][j] = -1e30f; l_run[i][j] = 0.f;
            #pragma unroll
            for (int q = 0; q < 4; q++) O[i][j][q] = 0.f;
        }

    uint32_t qoff[2];
    #pragma unroll
    for (int mf = 0; mf < 2; mf++) {
        const int row = wm * 32 + mf * 16 + (lg & 1) * 8 + lr8;
        qoff[mf] = smb + (uint32_t)(AQ_B + row * QROWB + (lg >> 1) * 16);
    }
    // V trans-ldmatrix lane mapping: tile = lid>>3 (0..3)
    //   tile0: t 0-7,  d grp0 | tile1: t 8-15, d grp0
    //   tile2: t 0-7,  d grp1 | tile3: t 8-15, d grp1
    const int vtile = lid >> 3;
    const int vt_off = (vtile & 1) * 8 + (lid & 7);
    const int vd_off = (vtile >> 1) * 8;
    const uint32_t voff_base =
        smb + (uint32_t)(AKV_B + vt_off * QROWB + (wn * 16 + vd_off) * 2);

    const float C1L = 0.18033688011112042f;    // 0.125 * log2(e)
    const int kmax_g = t0 + wm * 32 + 32;      // keys beyond have P=0 for this warp

    for (int c = 0; c < nchunks; c++) {
        const int s0 = c << 7;
        const int sc = min(128, S_lim - s0);       // 64 or 128
        const int NWc = sc >> 2;                   // 16 or 32
        const int nfmax = NWc >> 3;                // 2 or 4
        const int npair = nfmax >> 1;              // 1 or 2
        const int t_hi = t0 + wm * 32 + 31;

        // ---- load K chunk ----
        for (int idx = tid; idx < sc * 8; idx += 256) {
            const int s = idx >> 3, cc = idx & 7;
            *(uint4*)(smc + AKV_B + s * QROWB + cc * 16) =
                *(const uint4*)(kp + (size_t)(s0 + s) * D + cc * 8);
        }
        __syncthreads();

        // ---- QK^T ----
        float acc[2][4][4];
        #pragma unroll
        for (int i = 0; i < 2; i++)
            #pragma unroll
            for (int j = 0; j < 4; j++)
                #pragma unroll
                for (int q = 0; q < 4; q++) acc[i][j][q] = 0.f;

        #pragma unroll
        for (int ks = 0; ks < 4; ks++) {
            const uint32_t kb = (uint32_t)ks * 32;
            uint32_t af[2][4];
            #pragma unroll
            for (int mf = 0; mf < 2; mf++)
                LDM4(af[mf][0], af[mf][1], af[mf][2], af[mf][3], qoff[mf] + kb);
            #pragma unroll
            for (int p = 0; p < 2; p++) {
                if (p >= npair) break;
                const int n_lo = wn * NWc + p * 16;
                const int n_abs = s0 + n_lo;
                if (n_abs > t_hi) continue;
                const int rowk = n_lo + (lg >> 1) * 8 + lr8;
                uint32_t bf[4];
                LDM4(bf[0], bf[1], bf[2], bf[3],
                     smb + (uint32_t)(AKV_B + rowk * QROWB + (lg & 1) * 16) + kb);
                #pragma unroll
                for (int mf = 0; mf < 2; mf++) {
                    mma_f16(acc[mf][2 * p],     af[mf], &bf[0]);
                    if (n_abs + 8 <= t_hi)
                        mma_f16(acc[mf][2 * p + 1], af[mf], &bf[2]);
                }
            }
        }

        // ---- mask + per-warp max ----
        #pragma unroll
        for (int mf = 0; mf < 2; mf++) {
            const int r0 = wm * 32 + mf * 16 + gid;
            const int tg0 = t0 + r0, tg1 = tg0 + 8;
            float w0 = -1e30f, w1 = -1e30f;
            #pragma unroll
            for (int nf = 0; nf < 4; nf++) {
                if (nf >= nfmax) break;
                const int sA = s0 + wn * NWc + nf * 8 + 2 * tig;
                float* a = acc[mf][nf];
                a[0] = (sA     <= tg0) ? a[0] : -1e30f;
                a[1] = (sA + 1 <= tg0) ? a[1] : -1e30f;
                a[2] = (sA     <= tg1) ? a[2] : -1e30f;
                a[3] = (sA + 1 <= tg1) ? a[3] : -1e30f;
                w0 = fmaxf(w0, fmaxf(a[0], a[1]));
                w1 = fmaxf(w1, fmaxf(a[2], a[3]));
            }
            w0 = fmaxf(w0, __shfl_xor_sync(0xffffffffu, w0, 1));
            w0 = fmaxf(w0, __shfl_xor_sync(0xffffffffu, w0, 2));
            w1 = fmaxf(w1, __shfl_xor_sync(0xffffffffu, w1, 1));
            w1 = fmaxf(w1, __shfl_xor_sync(0xffffffffu, w1, 2));
            if (tig == 0) {
                pmx[wn * 64 + r0]     = w0;
                pmx[wn * 64 + r0 + 8] = w1;
            }
        }
        __syncthreads();

        // ---- rescale + exp + store P (fp16) + partial sums ----
        #pragma unroll
        for (int mf = 0; mf < 2; mf++) {
            const int r0 = wm * 32 + mf * 16 + gid;
            #pragma unroll
            for (int half = 0; half < 2; half++) {
                const int lrow = r0 + half * 8;
                float mc = fmaxf(fmaxf(pmx[lrow], pmx[64 + lrow]),
                                 fmaxf(pmx[128 + lrow], pmx[192 + lrow]));
                float mnew = fmaxf(m_run[mf][half], mc);
                float alpha = ex2f((m_run[mf][half] - mnew) * C1L);
                m_run[mf][half] = mnew;
                l_run[mf][half] *= alpha;
                #pragma unroll
                for (int nf = 0; nf < 2; nf++) {
                    O[mf][nf][half * 2 + 0] *= alpha;
                    O[mf][nf][half * 2 + 1] *= alpha;
                }
                float ps = 0.f;
                #pragma unroll
                for (int nf = 0; nf < 4; nf++) {
                    if (nf >= nfmax) break;
                    const int sl = wn * NWc + nf * 8 + 2 * tig;
                    float* a = acc[mf][nf];
                    float e0 = ex2f((a[half * 2 + 0] - mnew) * C1L);
                    float e1 = ex2f((a[half * 2 + 1] - mnew) * C1L);
                    ps += e0 + e1;
                    *(__half2*)(smc + AS_B + lrow * CROWB + sl * 2) =
                        __floats2half2_rn(e0, e1);
                }
                ps += __shfl_xor_sync(0xffffffffu, ps, 1);
                ps += __shfl_xor_sync(0xffffffffu, ps, 2);
                if (tig == 0) psm[wn * 64 + lrow] = ps;
            }
        }
        __syncthreads();   // St/psm ready; K dead

        // ---- load V chunk into KV ([t][d], same as K) + l update ----
        for (int idx = tid; idx < sc * 8; idx += 256) {
            const int s = idx >> 3, cc = idx & 7;
            *(uint4*)(smc + AKV_B + s * QROWB + cc * 16) =
                *(const uint4*)(vp + (size_t)(s0 + s) * D + cc * 8);
        }
        #pragma unroll
        for (int mf = 0; mf < 2; mf++) {
            const int r0 = wm * 32 + mf * 16 + gid;
            #pragma unroll
            for (int half = 0; half < 2; half++) {
                const int lrow = r0 + half * 8;
                l_run[mf][half] += psm[lrow] + psm[64 + lrow] +
                                   psm[128 + lrow] + psm[192 + lrow];
            }
        }
        __syncthreads();   // V ready

        // ---- PV accumulate: A = St rows, B = V via trans-ldmatrix ----
        {
            uint32_t soff[2];
            #pragma unroll
            for (int mf = 0; mf < 2; mf++) {
                const int row = wm * 32 + mf * 16 + (lg & 1) * 8 + lr8;
                soff[mf] = smb + (uint32_t)(AS_B + row * CROWB + (lg >> 1) * 16);
            }
            const int kloc = min(sc, kmax_g - s0);     // nonzero P cols (mult of 16)
            const int kst = kloc >> 4;
            for (int ks = 0; ks < kst; ks++) {
                uint32_t af[2][4], bf[4];
                // B: 16 t-rows x 16 d-cols, transposed tiles
                LDM4T(bf[0], bf[1], bf[2], bf[3],
                      voff_base + (uint32_t)(ks * 16) * QROWB);
                const uint32_t kb = (uint32_t)ks * 32;   // St col advance (16 halfs)
                #pragma unroll
                for (int mf = 0; mf < 2; mf++) {
                    LDM4(af[mf][0], af[mf][1], af[mf][2], af[mf][3], soff[mf] + kb);
                    mma_f16(O[mf][0], af[mf], &bf[0]);
                    mma_f16(O[mf][1], af[mf], &bf[2]);
                }
            }
        }
        __syncthreads();   // KV/St free for next chunk
    }

    // ---- epilogue: /l, cvt fp16, write g_attn ----
    #pragma unroll
    for (int mf = 0; mf < 2; mf++) {
        const int row0 = wm * 32 + mf * 16 + gid;
        #pragma unroll
        for (int half = 0; half < 2; half++) {
            const int i = row0 + half * 8;
            const float inv = 1.f / l_run[mf][half];
            #pragma unroll
            for (int nf = 0; nf < 2; nf++) {
                const int col = wn * 16 + nf * 8 + 2 * tig;
                *(__half2*)(g_attn + ((size_t)bb * T + t0 + i) * C + hh * D + col) =
                    __floats2half2_rn(O[mf][nf][half * 2 + 0] * inv,
                                      O[mf][nf][half * 2 + 1] * inv);
            }
        }
    }
}

// ---------------------------------------------------------------------------
extern "C" void kernel_launch(void* const* d_in, const int* in_sizes, int n_in,
                              void* d_out, int out_size)
{
    const float* x  = (const float*)d_in[0];
    const float* wq = (const float*)d_in[1];
    const float* wk = (const float*)d_in[2];
    const float* wv = (const float*)d_in[3];
    const float* bq = (const float*)d_in[4];
    const float* bk = (const float*)d_in[5];
    const float* bv = (const float*)d_in[6];
    const float* wo = (const float*)d_in[7];
    const float* bo = (const float*)d_in[8];
    float* out = (float*)d_out;

    cudaFuncSetAttribute(attn_kernel, cudaFuncAttributeMaxDynamicSharedMemorySize,
                         SMEM_ATTN);
    cudaFuncSetAttribute(gemm_mma_kernel, cudaFuncAttributeMaxDynamicSharedMemorySize,
                         SMEM_GEMM_BYTES);

    prep_kernel<<<PREP_BLOCKS, 256>>>((const float4*)x, wq, wk, wv, wo, bq, bk, bv);
    gemm_mma_kernel<<<dim3(N3 / 128, M / 128), 256, SMEM_GEMM_BYTES>>>(nullptr, nullptr, 0);
    attn_kernel<<<dim3(T / 64, H, B), 256, SMEM_ATTN>>>();
    gemm_mma_kernel<<<dim3(C / 128, M / 128), 256, SMEM_GEMM_BYTES>>>(bo, out, 1);
}